// round 2
// baseline (speedup 1.0000x reference)
#include <cuda_runtime.h>
#include <cuda_bf16.h>

// Embedding gather: out[n, :] = embeddings[inputs[n], :]
// N = 16384, EMB = 128 floats (512 bytes/row), VOCAB = 32000.
// One warp per row; each lane moves one float4 (16 B). 32 * 16 B = 512 B = one row.

#define N_ROWS   16384
#define EMB_F4   32          // 128 floats = 32 float4 per row
#define THREADS  256         // 8 warps per block -> 8 rows per block

__global__ __launch_bounds__(THREADS)
void onehot_embed_gather(const int* __restrict__ idx,
                         const float4* __restrict__ emb,   // [VOCAB, 32] float4
                         float4* __restrict__ out)          // [N, 32] float4
{
    const int tid  = blockIdx.x * THREADS + threadIdx.x;
    const int row  = tid >> 5;          // warp id = output row
    const int lane = tid & 31;          // float4 slot within row
    if (row >= N_ROWS) return;

    const int e = idx[row];             // broadcast within warp (same address all lanes? no —
                                        // each lane reads idx[row]; coalesces to 1 sector, L1 hit)
    out[row * EMB_F4 + lane] = emb[(long long)e * EMB_F4 + lane];
}

extern "C" void kernel_launch(void* const* d_in, const int* in_sizes, int n_in,
                              void* d_out, int out_size)
{
    const int*    idx = (const int*)   d_in[0];   // inputs: int32 [16384]
    const float4* emb = (const float4*)d_in[1];   // embeddings: float32 [32000,128]
    float4*       out = (float4*)      d_out;     // float32 [16384,128]

    const int total_threads = N_ROWS * 32;        // one warp per row
    const int blocks = (total_threads + THREADS - 1) / THREADS;  // 2048
    onehot_embed_gather<<<blocks, THREADS>>>(idx, emb, out);
}

// round 3
// speedup vs baseline: 1.0386x; 1.0386x over previous
#include <cuda_runtime.h>
#include <cuda_bf16.h>

// Embedding gather: out[n, :] = embeddings[inputs[n], :]
// N = 16384 rows, EMB = 128 floats = 32 float4 per row.
// Flat view: 16384*32 = 524288 float4 elements to produce.
// Each thread produces U=4 float4s, with all loads batched for MLP.

#define N_ROWS    16384
#define EMB_F4    32                      // float4 per row
#define TOTAL_F4  (N_ROWS * EMB_F4)       // 524288
#define THREADS   256
#define U         4
#define NTHREADS_TOTAL (TOTAL_F4 / U)     // 131072
#define NBLOCKS   (NTHREADS_TOTAL / THREADS)  // 512

__global__ __launch_bounds__(THREADS)
void onehot_embed_gather_mlp(const int* __restrict__ idx,
                             const float4* __restrict__ emb,   // [VOCAB, 32]
                             float4* __restrict__ out)          // [N, 32]
{
    const int tid = blockIdx.x * THREADS + threadIdx.x;

    // Phase 1: batched index loads (4 independent LDGs in flight)
    int pos[U];
    int e[U];
    #pragma unroll
    for (int u = 0; u < U; u++) {
        pos[u] = tid + u * NTHREADS_TOTAL;      // stride keeps warps coalesced
        e[u]   = idx[pos[u] >> 5];              // row index for this element
    }

    // Phase 2: batched gather loads (4 independent 16B LDGs in flight)
    float4 v[U];
    #pragma unroll
    for (int u = 0; u < U; u++) {
        const int lane = pos[u] & (EMB_F4 - 1);
        v[u] = emb[(long long)e[u] * EMB_F4 + lane];
    }

    // Phase 3: coalesced stores
    #pragma unroll
    for (int u = 0; u < U; u++) {
        out[pos[u]] = v[u];
    }
}

extern "C" void kernel_launch(void* const* d_in, const int* in_sizes, int n_in,
                              void* d_out, int out_size)
{
    const int*    idx = (const int*)   d_in[0];   // int32 [16384]
    const float4* emb = (const float4*)d_in[1];   // float32 [32000,128]
    float4*       out = (float4*)      d_out;     // float32 [16384,128]

    onehot_embed_gather_mlp<<<NBLOCKS, THREADS>>>(idx, emb, out);
}